// round 7
// baseline (speedup 1.0000x reference)
#include <cuda_runtime.h>
#include <cuda_bf16.h>
#include <math.h>
#include <stdint.h>

#define S_TOTAL 8192
#define DM      1024
#define NHEAD   16
#define HDIM    64
#define CHUNKL  2048
#define NCHUNK  4

// ---------------- scratch (allocation-free rule: __device__ globals) --------
__device__ float g_q[S_TOTAL * DM];
__device__ float g_k[S_TOTAL * DM];
__device__ float g_v[S_TOTAL * DM];
__device__ float g_attn[S_TOTAL * DM];
__device__ __nv_bfloat16 g_xhi[S_TOTAL * DM];
__device__ __nv_bfloat16 g_xlo[S_TOTAL * DM];
__device__ __nv_bfloat16 g_ahi[S_TOTAL * DM];
__device__ __nv_bfloat16 g_alo[S_TOTAL * DM];
__device__ __nv_bfloat16 g_whi[4 * DM * DM];
__device__ __nv_bfloat16 g_wlo[4 * DM * DM];

// ---------------- warp-mma helpers (plain sm_103-safe PTX) ------------------
__device__ __forceinline__ uint32_t smem_u32(const void* p) {
    uint32_t a;
    asm("{ .reg .u64 t; cvta.to.shared.u64 t, %1; cvt.u32.u64 %0, t; }" : "=r"(a) : "l"(p));
    return a;
}
__device__ __forceinline__ void ldsm_x4(uint32_t* r, uint32_t addr) {
    asm volatile("ldmatrix.sync.aligned.m8n8.x4.shared.b16 {%0,%1,%2,%3}, [%4];"
                 : "=r"(r[0]), "=r"(r[1]), "=r"(r[2]), "=r"(r[3]) : "r"(addr));
}
__device__ __forceinline__ void mma_bf16(float* c, const uint32_t* a, const uint32_t* b) {
    asm volatile("mma.sync.aligned.m16n8k16.row.col.f32.bf16.bf16.f32 "
                 "{%0,%1,%2,%3}, {%4,%5,%6,%7}, {%8,%9}, {%0,%1,%2,%3};"
                 : "+f"(c[0]), "+f"(c[1]), "+f"(c[2]), "+f"(c[3])
                 : "r"(a[0]), "r"(a[1]), "r"(a[2]), "r"(a[3]), "r"(b[0]), "r"(b[1]));
}
__device__ __forceinline__ void cp_async16(uint32_t saddr, const void* gaddr) {
    asm volatile("cp.async.cg.shared.global [%0], [%1], 16;" :: "r"(saddr), "l"(gaddr));
}

// ---------------- fp32 -> bf16 hi/lo split ----------------------------------
__global__ void __launch_bounds__(256) split_hi_lo(const float* __restrict__ src,
                                                   __nv_bfloat16* __restrict__ hi,
                                                   __nv_bfloat16* __restrict__ lo,
                                                   int n4) {
    int i = blockIdx.x * 256 + threadIdx.x;
    if (i >= n4) return;
    float4 v = ((const float4*)src)[i];
    float f[4] = {v.x, v.y, v.z, v.w};
    __align__(8) __nv_bfloat16 h[4], l[4];
#pragma unroll
    for (int j = 0; j < 4; j++) {
        h[j] = __float2bfloat16(f[j]);
        l[j] = __float2bfloat16(f[j] - __bfloat162float(h[j]));
    }
    ((uint2*)hi)[i] = *(uint2*)h;
    ((uint2*)lo)[i] = *(uint2*)l;
}

// ---------------- mma.sync GEMM, cp.async double-buffered -------------------
// C[m,n] = sum_k A[m,k]*B[n,k];  C = AhiBhi + AhiBlo + AloBhi (fp32 accum).
// Block 128(M)x64(N), BK=32. 8 warps as 2(M)x4(N); warp tile 64x16.
// Smem rows padded to 80B: rows 0..7 hit distinct banks for ldmatrix.
#define BM 128
#define BN 64
#define BKC 32
// per-stage layout (bytes): Ahi@0 (10240) Alo@10240 Bhi@20480 (5120) Blo@25600
#define STAGE_BYTES 30720
#define GEMM_SMEM   (2 * STAGE_BYTES)

__device__ __forceinline__ void gemm_prefetch(
    uint32_t stb, const __nv_bfloat16* const* aS, const __nv_bfloat16* const* bS,
    int bm, int bn, int kc, int K, int tid) {
#pragma unroll
    for (int s = 0; s < 2; s++) {
#pragma unroll
        for (int it = 0; it < 2; it++) {
            int id = tid + it * 256;                 // 0..511
            int row = id >> 2, c16 = (id & 3) * 16;  // 128 rows x 4 chunks
            cp_async16(stb + s * 10240 + row * 80 + c16,
                       aS[s] + (size_t)(bm * BM + row) * K + kc + (c16 >> 1));
        }
        {
            int row = tid >> 2, c16 = (tid & 3) * 16; // 64 rows x 4 chunks
            cp_async16(stb + 20480 + s * 5120 + row * 80 + c16,
                       bS[s] + (size_t)(bn * BN + row) * K + kc + (c16 >> 1));
        }
    }
}

__global__ void __launch_bounds__(256, 2) gemm_mma(
    const __nv_bfloat16* __restrict__ Ahi, const __nv_bfloat16* __restrict__ Alo,
    const __nv_bfloat16* __restrict__ Bhi, const __nv_bfloat16* __restrict__ Blo,
    float* __restrict__ C, int M, int N, int K) {
    extern __shared__ __align__(16) char smem[];
    const uint32_t sbase = smem_u32(smem);

    const int tid  = threadIdx.x;
    const int lane = tid & 31;
    const int warp = tid >> 5;
    const int wm = (warp & 1) * 64;
    const int wn = (warp >> 1) * 16;
    const int bm = blockIdx.x, bn = blockIdx.y;

    const uint32_t arow_off = (uint32_t)(wm + (lane & 15)) * 80 + (lane >> 4) * 16;
    const uint32_t bn_off =
        (uint32_t)(wn + (lane & 7) + ((lane >> 4) << 3)) * 80 + ((lane >> 3) & 1) * 16;

    const __nv_bfloat16* aS[2] = {Ahi, Alo};
    const __nv_bfloat16* bS[2] = {Bhi, Blo};

    float c[4][2][4];
#pragma unroll
    for (int i = 0; i < 4; i++)
#pragma unroll
        for (int j = 0; j < 2; j++)
#pragma unroll
            for (int t = 0; t < 4; t++) c[i][j][t] = 0.f;

    const int nk = K / BKC;

    gemm_prefetch(sbase, aS, bS, bm, bn, 0, K, tid);
    asm volatile("cp.async.commit_group;");

    for (int kc = 0; kc < nk; kc++) {
        const int st = kc & 1;
        if (kc + 1 < nk) {
            gemm_prefetch(sbase + (st ^ 1) * STAGE_BYTES, aS, bS, bm, bn,
                          (kc + 1) * BKC, K, tid);
            asm volatile("cp.async.commit_group;");
            asm volatile("cp.async.wait_group 1;");
        } else {
            asm volatile("cp.async.wait_group 0;");
        }
        __syncthreads();

        const uint32_t aHi = sbase + st * STAGE_BYTES + arow_off;
        const uint32_t bHi = sbase + st * STAGE_BYTES + 20480 + bn_off;

#pragma unroll
        for (int ks = 0; ks < 2; ks++) {
            uint32_t ah[4][4], al[4][4], bh[4], bl[4];
#pragma unroll
            for (int mt = 0; mt < 4; mt++)
                ldsm_x4(ah[mt], aHi + mt * (16 * 80) + ks * 32);
            ldsm_x4(bh, bHi + ks * 32);
#pragma unroll
            for (int mt = 0; mt < 4; mt++)
                ldsm_x4(al[mt], aHi + 10240 + mt * (16 * 80) + ks * 32);
            ldsm_x4(bl, bHi + 5120 + ks * 32);

#pragma unroll
            for (int mt = 0; mt < 4; mt++)
#pragma unroll
                for (int nt = 0; nt < 2; nt++) {
                    mma_bf16(c[mt][nt], ah[mt], &bh[nt * 2]);   // hi*hi
                    mma_bf16(c[mt][nt], ah[mt], &bl[nt * 2]);   // hi*lo
                    mma_bf16(c[mt][nt], al[mt], &bh[nt * 2]);   // lo*hi
                }
        }
        __syncthreads();
    }

    const int r0 = bm * BM + wm + (lane >> 2);
    const int c0 = bn * BN + wn + (lane & 3) * 2;
#pragma unroll
    for (int mt = 0; mt < 4; mt++)
#pragma unroll
        for (int nt = 0; nt < 2; nt++) {
            const int row = r0 + mt * 16;
            const int col = c0 + nt * 8;
            *(float2*)&C[(size_t)row * N + col]       = make_float2(c[mt][nt][0], c[mt][nt][1]);
            *(float2*)&C[(size_t)(row + 8) * N + col] = make_float2(c[mt][nt][2], c[mt][nt][3]);
        }
}

// ---------------- chunk-local causal attention (fp32, lane-pair split) ------
// 128 threads: lane pair (t, t^1) shares one query; each handles 32 of 64 dims.
__global__ void __launch_bounds__(128) attn_kernel(const float* __restrict__ q,
                                                   const float* __restrict__ k,
                                                   const float* __restrict__ v,
                                                   float* __restrict__ o) {
    __shared__ float KV[64][64];
    __shared__ float Sc[64][65];

    const int t    = threadIdx.x;
    const int qloc = t >> 1;      // 0..63
    const int half = t & 1;       // 0/1: dims [half*32, half*32+32)
    const int qb = blockIdx.x;
    const int h  = blockIdx.y;
    const int ch = blockIdx.z;

    const int    qi   = qb * 64 + qloc;
    const size_t qrow = (size_t)(ch * CHUNKL + qi) * DM + h * HDIM + half * 32;

    float qreg[32];
#pragma unroll
    for (int d = 0; d < 32; d += 4) {
        float4 x = *(const float4*)(q + qrow + d);
        qreg[d] = x.x; qreg[d + 1] = x.y; qreg[d + 2] = x.z; qreg[d + 3] = x.w;
    }

    float m = -INFINITY, l = 0.f;
    float acc[32];
#pragma unroll
    for (int d = 0; d < 32; d++) acc[d] = 0.f;

    for (int kb = 0; kb <= qb; kb++) {
        const size_t tbase = (size_t)(ch * CHUNKL + kb * 64) * DM + h * HDIM;

        __syncthreads();
#pragma unroll
        for (int i = 0; i < 8; i++) {
            int idx = t + i * 128;
            int j = idx >> 4, d4 = (idx & 15) << 2;
            *(float4*)&KV[j][d4] = *(const float4*)(k + tbase + (size_t)j * DM + d4);
        }
        __syncthreads();

        // pass 1: scores (pair-split dot + shuffle combine)
        float mtile = -INFINITY;
#pragma unroll 4
        for (int j = 0; j < 64; j++) {
            float d0 = 0.f;
#pragma unroll
            for (int d = 0; d < 32; d += 4) {
                float4 kv = *(const float4*)&KV[j][half * 32 + d];
                d0 += qreg[d] * kv.x + qreg[d + 1] * kv.y
                    + qreg[d + 2] * kv.z + qreg[d + 3] * kv.w;
            }
            d0 += __shfl_xor_sync(0xffffffffu, d0, 1);
            const int kidx = kb * 64 + j;
            const float s = (kidx > qi) ? -1e30f : d0 * 0.125f;
            Sc[qloc][j] = s;          // both halves write same value
            mtile = fmaxf(mtile, s);
        }

        const float mnew = fmaxf(m, mtile);
        const float corr = __expf(m - mnew);
        l *= corr;
#pragma unroll
        for (int d = 0; d < 32; d++) acc[d] *= corr;
        m = mnew;

        __syncthreads();
#pragma unroll
        for (int i = 0; i < 8; i++) {
            int idx = t + i * 128;
            int j = idx >> 4, d4 = (idx & 15) << 2;
            *(float4*)&KV[j][d4] = *(const float4*)(v + tbase + (size_t)j * DM + d4);
        }
        __syncthreads();

        // pass 2: probs + V accumulation (32 dims per thread)
#pragma unroll 2
        for (int j = 0; j < 64; j++) {
            const float sv = Sc[qloc][j];
            const float p = (sv > -1e29f) ? __expf(sv - m) : 0.f;
            l += p;
#pragma unroll
            for (int d = 0; d < 32; d += 4) {
                float4 vv = *(const float4*)&KV[j][half * 32 + d];
                acc[d]     += p * vv.x;
                acc[d + 1] += p * vv.y;
                acc[d + 2] += p * vv.z;
                acc[d + 3] += p * vv.w;
            }
        }
    }

    const float inv = 1.f / l;
#pragma unroll
    for (int d = 0; d < 32; d += 4) {
        float4 x;
        x.x = acc[d] * inv;     x.y = acc[d + 1] * inv;
        x.z = acc[d + 2] * inv; x.w = acc[d + 3] * inv;
        *(float4*)(o + qrow + d) = x;
    }
}

// ---------------------------------------------------------------------------
extern "C" void kernel_launch(void* const* d_in, const int* in_sizes, int n_in,
                              void* d_out, int out_size) {
    const float* x  = (const float*)d_in[0];
    const float* Wq = (const float*)d_in[1];
    const float* Wk = (const float*)d_in[2];
    const float* Wv = (const float*)d_in[3];
    const float* Wo = (const float*)d_in[4];
    float* out = (float*)d_out;

    float *q, *k, *v, *a;
    __nv_bfloat16 *xhi, *xlo, *ahi, *alo, *whi, *wlo;
    cudaGetSymbolAddress((void**)&q, g_q);
    cudaGetSymbolAddress((void**)&k, g_k);
    cudaGetSymbolAddress((void**)&v, g_v);
    cudaGetSymbolAddress((void**)&a, g_attn);
    cudaGetSymbolAddress((void**)&xhi, g_xhi);
    cudaGetSymbolAddress((void**)&xlo, g_xlo);
    cudaGetSymbolAddress((void**)&ahi, g_ahi);
    cudaGetSymbolAddress((void**)&alo, g_alo);
    cudaGetSymbolAddress((void**)&whi, g_whi);
    cudaGetSymbolAddress((void**)&wlo, g_wlo);

    cudaFuncSetAttribute(gemm_mma, cudaFuncAttributeMaxDynamicSharedMemorySize, GEMM_SMEM);

    const int nx4 = S_TOTAL * DM / 4;
    const int nw4 = DM * DM / 4;
    const float* Ws[4] = {Wq, Wk, Wv, Wo};

    split_hi_lo<<<(nx4 + 255) / 256, 256>>>(x, xhi, xlo, nx4);
    for (int i = 0; i < 4; i++)
        split_hi_lo<<<(nw4 + 255) / 256, 256>>>(Ws[i], whi + (size_t)i * DM * DM,
                                                wlo + (size_t)i * DM * DM, nw4);

    dim3 gg(S_TOTAL / BM, DM / BN);   // (64, 16)
    gemm_mma<<<gg, 256, GEMM_SMEM>>>(xhi, xlo, whi + 0 * (size_t)DM * DM,
                                     wlo + 0 * (size_t)DM * DM, q, S_TOTAL, DM, DM);
    gemm_mma<<<gg, 256, GEMM_SMEM>>>(xhi, xlo, whi + 1 * (size_t)DM * DM,
                                     wlo + 1 * (size_t)DM * DM, k, S_TOTAL, DM, DM);
    gemm_mma<<<gg, 256, GEMM_SMEM>>>(xhi, xlo, whi + 2 * (size_t)DM * DM,
                                     wlo + 2 * (size_t)DM * DM, v, S_TOTAL, DM, DM);

    attn_kernel<<<dim3(CHUNKL / 64, NHEAD, NCHUNK), 128>>>(q, k, v, a);

    split_hi_lo<<<(nx4 + 255) / 256, 256>>>(a, ahi, alo, nx4);
    gemm_mma<<<gg, 256, GEMM_SMEM>>>(ahi, alo, whi + 3 * (size_t)DM * DM,
                                     wlo + 3 * (size_t)DM * DM, out, S_TOTAL, DM, DM);
}